// round 4
// baseline (speedup 1.0000x reference)
#include <cuda_runtime.h>

#define NU 100000
#define NI 50000
#define NN 150000
#define DD 64
#define EG 3200000
#define EU_ 1600000
#define EI_ 800000

typedef unsigned long long ull;

// ---------------- device scratch ----------------
__device__ float g_cur[NN * DD];
__device__ float g_gnn[NN * DD];
__device__ float g_total[NN * DD];
__device__ float g_z[NN * 2 * DD];      // row = node*2 + metapath; user block then item block
__device__ float g_deg[(NU + NI) * 4];
__device__ float g_wsum[4];

__device__ __forceinline__ void red_add_v4(float* addr, float4 v) {
    asm volatile("red.global.add.v4.f32 [%0], {%1,%2,%3,%4};"
                 :: "l"(addr), "f"(v.x), "f"(v.y), "f"(v.z), "f"(v.w)
                 : "memory");
}

// f32x2 packed math (sm_100+)
__device__ __forceinline__ ull pk2(float a) {
    ull r;
    asm("mov.b64 %0, {%1, %1};" : "=l"(r) : "f"(a));
    return r;
}
__device__ __forceinline__ ull pack2(float lo, float hi) {
    ull r;
    asm("mov.b64 %0, {%1, %2};" : "=l"(r) : "f"(lo), "f"(hi));
    return r;
}
__device__ __forceinline__ void fma2(ull& d, ull a, ull b) {
    asm("fma.rn.f32x2 %0, %1, %2, %0;" : "+l"(d) : "l"(a), "l"(b));
}
__device__ __forceinline__ float2 up2(ull v) {
    float2 f;
    asm("mov.b64 {%0, %1}, %2;" : "=f"(f.x), "=f"(f.y) : "l"(v));
    return f;
}

// ---------------- init / zero ----------------
__global__ void __launch_bounds__(256) k_init(const float* __restrict__ fu,
                                              const float* __restrict__ fi) {
    unsigned i = blockIdx.x * 256u + threadIdx.x;
    if (i < NU * DD) {
        float v = fu[i];
        g_cur[i] = v; g_total[i] = v;
    } else if (i < NN * DD) {
        float v = fi[i - NU * DD];
        g_cur[i] = v; g_total[i] = v;
    }
}

__global__ void __launch_bounds__(256) k_zero_gnn() {
    unsigned i = blockIdx.x * 256u + threadIdx.x;
    if (i < NN * DD) g_gnn[i] = 0.f;
}

__global__ void __launch_bounds__(256) k_zero_han() {
    unsigned i = blockIdx.x * 256u + threadIdx.x;
    if (i < (unsigned)(NN * 2 * DD)) g_z[i] = 0.f;
    if (i < (unsigned)((NU + NI) * 4)) g_deg[i] = 0.f;
    if (i < 4u) g_wsum[i] = 0.f;
}

// ---------------- DCCF: SpMM gnn[row] += val * cur[col] ----------------
__global__ void __launch_bounds__(256) k_spmm(const int* __restrict__ G,
                                              const float* __restrict__ gv) {
    unsigned t = blockIdx.x * 256u + threadIdx.x;
    unsigned e = t >> 4;
    unsigned c = t & 15u;
    if (e >= EG) return;
    int row = __ldg(G + e);
    int col = __ldg(G + EG + e);
    float v = __ldg(gv + e);
    float4 x = *(const float4*)(g_cur + (size_t)col * DD + c * 4);
    red_add_v4(g_gnn + (size_t)row * DD + c * 4,
               make_float4(v * x.x, v * x.y, v * x.z, v * x.w));
}

// ---------------- DCCF: intent projection — row-pair f32x2, 8 rows/warp ----------------
// smem (floats):
//   Wp   [0 .. 8192)         W[k][4L..4L+3] float4 at k*32+L       (32 KB)
//   WTp  [8192 .. 16640)     {W[2L][j], W[2L+1][j]} float2 at j*33+L (33 KB, padded)
//   uT2  [16640 .. 20736)    8 warps * 256 u64  {u[2p][k],u[2p+1][k]} at p*64+k
//   pT2  [20736 .. 28928)    8 warps * 512 u64  {p[2p][j],p[2p+1][j]} at p*128+j
// total 28928 floats = 115712 B
#define INTENT_SMEM 115712
#define IT_THREADS 256
#define IT_ROWS_PER_BLOCK 64

__global__ void __launch_bounds__(IT_THREADS) k_intent(const float* __restrict__ Wu,
                                                       const float* __restrict__ Wi) {
    extern __shared__ float sm[];
    const float4* Wp4 = (const float4*)sm;
    const float2* WTp = (const float2*)(sm + 8192);
    const int tid = threadIdx.x, w = tid >> 5, lane = tid & 31;

    ull* uT2 = (ull*)(sm + 16640) + w * 256;
    ull* pT2 = (ull*)(sm + 20736) + w * 512;

    const int UB = (NU + IT_ROWS_PER_BLOCK - 1) / IT_ROWS_PER_BLOCK;  // 1563
    const bool isUser = (int)blockIdx.x < UB;
    const float* Wg = isUser ? Wu : Wi;
    const int rowbase = isUser ? (int)blockIdx.x * IT_ROWS_PER_BLOCK
                               : NU + ((int)blockIdx.x - UB) * IT_ROWS_PER_BLOCK;
    const int rowlim = isUser ? NU : NN;

    // stage 1: Wp (flat copy of W, also serves as k-major float4 view)
    for (int t = tid; t < 2048; t += IT_THREADS) {
        ((float4*)sm)[t] = ((const float4*)Wg)[t];
    }
    __syncthreads();
    // stage 2: WTp transpose from smem (conflict-free: lanes vary j)
    for (int t = tid; t < 4096; t += IT_THREADS) {
        int L = t >> 7, j = t & 127;
        ((float2*)(sm + 8192))[j * 33 + L] =
            make_float2(sm[(2 * L) * 128 + j], sm[(2 * L + 1) * 128 + j]);
    }
    __syncthreads();

    const int r0 = rowbase + w * 8;

    // load u transposed + row-paired
    for (int t = lane; t < 256; t += 32) {
        int rho = t >> 6, k = t & 63;
        int ra = r0 + 2 * rho, rb = ra + 1;
        float xa = (ra < rowlim) ? g_cur[(size_t)ra * DD + k] : 0.f;
        float xb = (rb < rowlim) ? g_cur[(size_t)rb * DD + k] : 0.f;
        uT2[rho * 64 + k] = pack2(xa, xb);
    }
    __syncwarp();

    // ---- pass 1: scores = u @ W.  acc[rho][c]: rows (2rho,2rho+1) packed, j = 4*lane+c
    ull acc[4][4];
#pragma unroll
    for (int a = 0; a < 4; a++) { acc[a][0] = acc[a][1] = acc[a][2] = acc[a][3] = 0ull; }

    const ulonglong2* uT2v = (const ulonglong2*)uT2;
#pragma unroll 4
    for (int k2 = 0; k2 < 32; k2++) {
        float4 wa = Wp4[(2 * k2) * 32 + lane];
        float4 wb = Wp4[(2 * k2 + 1) * 32 + lane];
        ull sa0 = pk2(wa.x), sa1 = pk2(wa.y), sa2 = pk2(wa.z), sa3 = pk2(wa.w);
        ull sb0 = pk2(wb.x), sb1 = pk2(wb.y), sb2 = pk2(wb.z), sb3 = pk2(wb.w);
#pragma unroll
        for (int rho = 0; rho < 4; rho++) {
            ulonglong2 up = uT2v[rho * 32 + k2];
            fma2(acc[rho][0], sa0, up.x); fma2(acc[rho][1], sa1, up.x);
            fma2(acc[rho][2], sa2, up.x); fma2(acc[rho][3], sa3, up.x);
            fma2(acc[rho][0], sb0, up.y); fma2(acc[rho][1], sb1, up.y);
            fma2(acc[rho][2], sb2, up.y); fma2(acc[rho][3], sb3, up.y);
        }
    }

    // ---- softmax per row (both parities), write pT2 ----
#pragma unroll
    for (int rho = 0; rho < 4; rho++) {
        float2 a0 = up2(acc[rho][0]), a1 = up2(acc[rho][1]);
        float2 a2 = up2(acc[rho][2]), a3 = up2(acc[rho][3]);
        float ml = fmaxf(fmaxf(a0.x, a1.x), fmaxf(a2.x, a3.x));
        float mh = fmaxf(fmaxf(a0.y, a1.y), fmaxf(a2.y, a3.y));
#pragma unroll
        for (int off = 16; off; off >>= 1) {
            ml = fmaxf(ml, __shfl_xor_sync(0xffffffffu, ml, off));
            mh = fmaxf(mh, __shfl_xor_sync(0xffffffffu, mh, off));
        }
        float el0 = __expf(a0.x - ml), el1 = __expf(a1.x - ml);
        float el2 = __expf(a2.x - ml), el3 = __expf(a3.x - ml);
        float eh0 = __expf(a0.y - mh), eh1 = __expf(a1.y - mh);
        float eh2 = __expf(a2.y - mh), eh3 = __expf(a3.y - mh);
        float sl = el0 + el1 + el2 + el3;
        float sh = eh0 + eh1 + eh2 + eh3;
#pragma unroll
        for (int off = 16; off; off >>= 1) {
            sl += __shfl_xor_sync(0xffffffffu, sl, off);
            sh += __shfl_xor_sync(0xffffffffu, sh, off);
        }
        float il = 1.f / sl, ih = 1.f / sh;
        ull q0 = pack2(el0 * il, eh0 * ih);
        ull q1 = pack2(el1 * il, eh1 * ih);
        ull q2 = pack2(el2 * il, eh2 * ih);
        ull q3 = pack2(el3 * il, eh3 * ih);
        ((ulonglong2*)pT2)[rho * 64 + 2 * lane] = make_ulonglong2(q0, q1);
        ((ulonglong2*)pT2)[rho * 64 + 2 * lane + 1] = make_ulonglong2(q2, q3);
    }
    __syncwarp();

    // ---- pass 2: out = p @ W^T.  acc2[rho][dc]: rows packed, dims d = 2*lane+dc
    ull acc2[4][2];
#pragma unroll
    for (int a = 0; a < 4; a++) { acc2[a][0] = 0ull; acc2[a][1] = 0ull; }

    const ulonglong2* pT2v = (const ulonglong2*)pT2;
#pragma unroll 2
    for (int j4 = 0; j4 < 32; j4++) {
        ulonglong2 P0a = pT2v[0 * 64 + 2 * j4], P0b = pT2v[0 * 64 + 2 * j4 + 1];
        ulonglong2 P1a = pT2v[1 * 64 + 2 * j4], P1b = pT2v[1 * 64 + 2 * j4 + 1];
        ulonglong2 P2a = pT2v[2 * 64 + 2 * j4], P2b = pT2v[2 * 64 + 2 * j4 + 1];
        ulonglong2 P3a = pT2v[3 * 64 + 2 * j4], P3b = pT2v[3 * 64 + 2 * j4 + 1];
#define P2J(JJ, PW)                                             \
        {                                                       \
            float2 wt = WTp[(4 * j4 + JJ) * 33 + lane];         \
            ull s0 = pk2(wt.x), s1 = pk2(wt.y);                 \
            fma2(acc2[0][0], s0, P0##PW); fma2(acc2[0][1], s1, P0##PW); \
            fma2(acc2[1][0], s0, P1##PW); fma2(acc2[1][1], s1, P1##PW); \
            fma2(acc2[2][0], s0, P2##PW); fma2(acc2[2][1], s1, P2##PW); \
            fma2(acc2[3][0], s0, P3##PW); fma2(acc2[3][1], s1, P3##PW); \
        }
        P2J(0, a.x) P2J(1, a.y) P2J(2, b.x) P2J(3, b.y)
#undef P2J
    }

    // ---- epilogue: residual + total ----
#pragma unroll
    for (int rho = 0; rho < 4; rho++) {
        float2 o0 = up2(acc2[rho][0]);  // {out[2rho][d0], out[2rho+1][d0]}
        float2 o1 = up2(acc2[rho][1]);  // {out[2rho][d1], out[2rho+1][d1]}
#pragma unroll
        for (int par = 0; par < 2; par++) {
            int r = r0 + 2 * rho + par;
            if (r >= rowlim) continue;
            float oa = par ? o0.y : o0.x;
            float ob = par ? o1.y : o1.x;
            size_t base = (size_t)r * DD + lane * 2;
            float2 cu = *(const float2*)(g_cur + base);
            float2 gn = *(const float2*)(g_gnn + base);
            float2 tt = *(const float2*)(g_total + base);
            float n0 = gn.x + oa + cu.x;
            float n1 = gn.y + ob + cu.y;
            *(float2*)(g_cur + base) = make_float2(n0, n1);
            *(float2*)(g_total + base) = make_float2(tt.x + n0, tt.y + n1);
        }
    }
}

// ---------------- HAN: degree counting ----------------
__global__ void __launch_bounds__(256) k_deg(const int* __restrict__ edges, int E2,
                                             int n, int degbase) {
    unsigned t = blockIdx.x * 256u + threadIdx.x;
    if (t >= 2u * (unsigned)E2) return;
    int m = (t >= (unsigned)E2) ? 1 : 0;
    int e = (int)t - m * E2;
    int src = __ldg(edges + (size_t)m * 2 * E2 + e);
    int dst = __ldg(edges + (size_t)m * 2 * E2 + E2 + e);
    atomicAdd(&g_deg[degbase + (2 * m + 0) * n + src], 1.f);
    atomicAdd(&g_deg[degbase + (2 * m + 1) * n + dst], 1.f);
}

// ---------------- HAN: scatter z[dst,m] += h[src] * rsqrt(deg_out[src]) ----------------
__global__ void __launch_bounds__(256) k_scatter(const int* __restrict__ edges, int E2,
                                                 int n, int degbase, int zbase,
                                                 const float* __restrict__ feat) {
    unsigned t = blockIdx.x * 256u + threadIdx.x;
    unsigned idx = t >> 4;
    unsigned c = t & 15u;
    if (idx >= 2u * (unsigned)E2) return;
    int m = (idx >= (unsigned)E2) ? 1 : 0;
    int e = (int)idx - m * E2;
    int src = __ldg(edges + (size_t)m * 2 * E2 + e);
    int dst = __ldg(edges + (size_t)m * 2 * E2 + E2 + e);
    float dout = g_deg[degbase + (2 * m) * n + src];
    float s = dout > 0.f ? rsqrtf(dout) : 0.f;
    float4 x = *(const float4*)(feat + (size_t)src * DD + c * 4);
    red_add_v4(g_z + (size_t)zbase + ((size_t)dst * 2 + m) * DD + c * 4,
               make_float4(x.x * s, x.y * s, x.z * s, x.w * s));
}

// ---------------- HAN: in-degree scale + semantic attention logits, 8 rows/warp ----------------
__global__ void __launch_bounds__(256) k_han_node(const float* __restrict__ W1g,
                                                  const float* __restrict__ b1g,
                                                  const float* __restrict__ w2g,
                                                  int n, int degbase, int zbase, int wbase) {
    __shared__ float Wsm[8192];
    __shared__ float ush[4096];   // 8 warps * 8 rows * 64
    __shared__ float bsh[128];
    __shared__ float w2sh[128];
    __shared__ float wacc[2];

    const int tid = threadIdx.x, w = tid >> 5, lane = tid & 31;
    for (int t = tid; t < 2048; t += 256) {
        int k = t >> 5, L = t & 31;
        ((float4*)Wsm)[t] = *(const float4*)(W1g + k * 128 + L * 4);
    }
    if (tid < 128) { bsh[tid] = b1g[tid]; w2sh[tid] = w2g[tid]; }
    if (tid < 2) wacc[tid] = 0.f;
    __syncthreads();

    const int rows = 2 * n;
    const int r0 = (int)blockIdx.x * 64 + w * 8;
    float* u = ush + w * 512;

    for (int t = lane; t < 512; t += 32) {
        int rr = t >> 6, d = t & 63;
        int row = r0 + rr;
        float v = 0.f;
        if (row < rows) {
            int node = row >> 1, m = row & 1;
            float din = g_deg[degbase + (2 * m + 1) * n + node];
            float s = din > 0.f ? rsqrtf(din) : 0.f;
            size_t zi = (size_t)zbase + (size_t)row * DD + d;
            v = g_z[zi] * s;
            g_z[zi] = v;  // persist scaled z for combine
        }
        u[t] = v;
    }
    __syncwarp();

    float acc[8][4];
#pragma unroll
    for (int a = 0; a < 8; a++) { acc[a][0] = acc[a][1] = acc[a][2] = acc[a][3] = 0.f; }

#pragma unroll 2
    for (int kk = 0; kk < 16; kk++) {
        float4 w0 = ((const float4*)Wsm)[(4 * kk + 0) * 32 + lane];
        float4 w1 = ((const float4*)Wsm)[(4 * kk + 1) * 32 + lane];
        float4 w2 = ((const float4*)Wsm)[(4 * kk + 2) * 32 + lane];
        float4 w3 = ((const float4*)Wsm)[(4 * kk + 3) * 32 + lane];
#pragma unroll
        for (int rr = 0; rr < 8; rr++) {
            float4 uv = *(const float4*)(u + rr * 64 + kk * 4);
            acc[rr][0] += uv.x * w0.x + uv.y * w1.x + uv.z * w2.x + uv.w * w3.x;
            acc[rr][1] += uv.x * w0.y + uv.y * w1.y + uv.z * w2.y + uv.w * w3.y;
            acc[rr][2] += uv.x * w0.z + uv.y * w1.z + uv.z * w2.z + uv.w * w3.z;
            acc[rr][3] += uv.x * w0.w + uv.y * w1.w + uv.z * w2.w + uv.w * w3.w;
        }
    }

    float wl01[2] = {0.f, 0.f};
#pragma unroll
    for (int rr = 0; rr < 8; rr++) {
        int row = r0 + rr;
        float wl = 0.f;
#pragma unroll
        for (int c = 0; c < 4; c++) {
            int j = lane * 4 + c;
            wl += tanhf(acc[rr][c] + bsh[j]) * w2sh[j];
        }
        if (row < rows) wl01[row & 1] += wl;
    }
#pragma unroll
    for (int off = 16; off; off >>= 1) {
        wl01[0] += __shfl_xor_sync(0xffffffffu, wl01[0], off);
        wl01[1] += __shfl_xor_sync(0xffffffffu, wl01[1], off);
    }
    if (lane == 0) {
        atomicAdd(&wacc[0], wl01[0]);
        atomicAdd(&wacc[1], wl01[1]);
    }
    __syncthreads();
    if (tid < 2) atomicAdd(&g_wsum[wbase + tid], wacc[tid]);
}

// ---------------- final combine: 0.5*dccf + 0.5*han ----------------
__global__ void __launch_bounds__(256) k_combine(float* __restrict__ out) {
    unsigned i = blockIdx.x * 256u + threadIdx.x;
    if (i >= (unsigned)(NN * DD)) return;
    unsigned node = i >> 6, d = i & 63u;
    float w0, w1;
    size_t zr;
    if (node < NU) {
        w0 = g_wsum[0] * (1.f / NU);
        w1 = g_wsum[1] * (1.f / NU);
        zr = (size_t)node * 128;
    } else {
        w0 = g_wsum[2] * (1.f / NI);
        w1 = g_wsum[3] * (1.f / NI);
        zr = (size_t)NU * 128 + (size_t)(node - NU) * 128;
    }
    float mx = fmaxf(w0, w1);
    float e0 = __expf(w0 - mx), e1 = __expf(w1 - mx);
    float inv = 1.f / (e0 + e1);
    float han = (e0 * inv) * g_z[zr + d] + (e1 * inv) * g_z[zr + 64 + d];
    out[i] = 0.5f * g_total[i] + 0.5f * han;
}

// ---------------- launcher ----------------
extern "C" void kernel_launch(void* const* d_in, const int* in_sizes, int n_in,
                              void* d_out, int out_size) {
    const int*   G    = (const int*)d_in[0];
    const float* Gv   = (const float*)d_in[1];
    const float* fu   = (const float*)d_in[2];
    const float* fi   = (const float*)d_in[3];
    const float* Wu   = (const float*)d_in[4];
    const float* Wi   = (const float*)d_in[5];
    const int*   eu   = (const int*)d_in[6];
    const int*   ei   = (const int*)d_in[7];
    const float* suW1 = (const float*)d_in[8];
    const float* sub1 = (const float*)d_in[9];
    const float* suw2 = (const float*)d_in[10];
    const float* siW1 = (const float*)d_in[11];
    const float* sib1 = (const float*)d_in[12];
    const float* siw2 = (const float*)d_in[13];
    float* out = (float*)d_out;

    cudaFuncSetAttribute(k_intent, cudaFuncAttributeMaxDynamicSharedMemorySize, INTENT_SMEM);

    const int UB = (NU + IT_ROWS_PER_BLOCK - 1) / IT_ROWS_PER_BLOCK;  // 1563
    const int IB = (NI + IT_ROWS_PER_BLOCK - 1) / IT_ROWS_PER_BLOCK;  // 782

    k_init<<<37500, 256>>>(fu, fi);
    for (int layer = 0; layer < 2; layer++) {
        k_zero_gnn<<<37500, 256>>>();
        k_spmm<<<200000, 256>>>(G, Gv);
        k_intent<<<UB + IB, IT_THREADS, INTENT_SMEM>>>(Wu, Wi);
    }
    k_zero_han<<<75000, 256>>>();
    k_deg<<<12500, 256>>>(eu, EU_, NU, 0);
    k_deg<<<6250, 256>>>(ei, EI_, NI, NU * 4);
    k_scatter<<<200000, 256>>>(eu, EU_, NU, 0, 0, fu);
    k_scatter<<<100000, 256>>>(ei, EI_, NI, NU * 4, NU * 128, fi);
    k_han_node<<<3125, 256>>>(suW1, sub1, suw2, NU, 0, 0, 0);
    k_han_node<<<1563, 256>>>(siW1, sib1, siw2, NI, NU * 4, NU * 128, 2);
    k_combine<<<37500, 256>>>(out);
}

// round 5
// speedup vs baseline: 1.8052x; 1.8052x over previous
#include <cuda_runtime.h>

#define NU 100000
#define NI 50000
#define NN 150000
#define DD 64
#define EG 3200000
#define EU_ 1600000
#define EI_ 800000

typedef unsigned long long ull;

// ---------------- device scratch ----------------
__device__ float g_cur[NN * DD];
__device__ float g_gnn[NN * DD];
__device__ float g_total[NN * DD];
__device__ float g_z[NN * 2 * DD];        // row = node*2 + metapath
__device__ float g_wsum[4];

// CSR for G
__device__ int    g_cntG[NN];
__device__ int    g_curG[NN];
__device__ int    g_rptrG[NN + 1];
__device__ float2 g_epayG[EG];            // {col_bits, val}

// CSR + degrees for HAN (4 graphs: u-mp0, u-mp1, i-mp0, i-mp1)
#define HN (2 * NU + 2 * NI)              // 300000 node-graph slots
__device__ int g_dout[HN];
__device__ int g_din[HN];
__device__ int g_curH[HN];
__device__ int g_rptrH[2 * (NU + 1) + 2 * (NI + 1)];
__device__ int g_hpay[2 * EU_ + 2 * EI_];

// f32x2 packed math (sm_100+)
__device__ __forceinline__ ull pk2(float a) {
    ull r;
    asm("mov.b64 %0, {%1, %1};" : "=l"(r) : "f"(a));
    return r;
}
__device__ __forceinline__ ull pack2(float lo, float hi) {
    ull r;
    asm("mov.b64 %0, {%1, %2};" : "=l"(r) : "f"(lo), "f"(hi));
    return r;
}
__device__ __forceinline__ void fma2(ull& d, ull a, ull b) {
    asm("fma.rn.f32x2 %0, %1, %2, %0;" : "+l"(d) : "l"(a), "l"(b));
}
__device__ __forceinline__ float2 up2(ull v) {
    float2 f;
    asm("mov.b64 {%0, %1}, %2;" : "=f"(f.x), "=f"(f.y) : "l"(v));
    return f;
}

// ---------------- zero counters ----------------
__global__ void __launch_bounds__(256) k_zero_cnt() {
    unsigned i = blockIdx.x * 256u + threadIdx.x;
    if (i < NN) { g_cntG[i] = 0; g_curG[i] = 0; }
    if (i < HN) { g_dout[i] = 0; g_din[i] = 0; g_curH[i] = 0; }
    if (i < 4u) g_wsum[i] = 0.f;
}

// ---------------- init ----------------
__global__ void __launch_bounds__(256) k_init(const float* __restrict__ fu,
                                              const float* __restrict__ fi) {
    unsigned i = blockIdx.x * 256u + threadIdx.x;
    if (i < NU * DD) {
        float v = fu[i];
        g_cur[i] = v; g_total[i] = v;
    } else if (i < NN * DD) {
        float v = fi[i - NU * DD];
        g_cur[i] = v; g_total[i] = v;
    }
}

// ---------------- CSR build: G histogram ----------------
__global__ void __launch_bounds__(256) k_histG(const int* __restrict__ G) {
    unsigned e = blockIdx.x * 256u + threadIdx.x;
    if (e >= EG) return;
    atomicAdd(&g_cntG[__ldg(G + e)], 1);
}

// ---------------- CSR build: HAN histograms (src + dst) ----------------
__global__ void __launch_bounds__(256) k_histH(const int* __restrict__ edges, int E2,
                                               int n, int base) {
    unsigned t = blockIdx.x * 256u + threadIdx.x;
    if (t >= 2u * (unsigned)E2) return;
    int m = (t >= (unsigned)E2) ? 1 : 0;
    int e = (int)t - m * E2;
    int src = __ldg(edges + (size_t)m * 2 * E2 + e);
    int dst = __ldg(edges + (size_t)m * 2 * E2 + E2 + e);
    atomicAdd(&g_dout[base + m * n + src], 1);
    atomicAdd(&g_din[base + m * n + dst], 1);
}

// ---------------- exclusive scans (5 segments, one block each) ----------------
__global__ void __launch_bounds__(1024) k_scan() {
    const int* cnt; int* rptr; int n;
    switch (blockIdx.x) {
        case 0: cnt = g_cntG;              rptr = g_rptrG;                          n = NN; break;
        case 1: cnt = g_din;               rptr = g_rptrH;                          n = NU; break;
        case 2: cnt = g_din + NU;          rptr = g_rptrH + (NU + 1);               n = NU; break;
        case 3: cnt = g_din + 2 * NU;      rptr = g_rptrH + 2 * (NU + 1);           n = NI; break;
        default: cnt = g_din + 2 * NU + NI; rptr = g_rptrH + 2 * (NU + 1) + (NI + 1); n = NI; break;
    }
    __shared__ int wsum[32];
    __shared__ int s_carry;
    const int tid = threadIdx.x, lane = tid & 31, wid = tid >> 5;
    if (tid == 0) s_carry = 0;
    __syncthreads();
    for (int base = 0; base < n; base += 1024) {
        int i = base + tid;
        int v = (i < n) ? cnt[i] : 0;
        int x = v;
#pragma unroll
        for (int off = 1; off < 32; off <<= 1) {
            int y = __shfl_up_sync(0xffffffffu, x, off);
            if (lane >= off) x += y;
        }
        if (lane == 31) wsum[wid] = x;
        __syncthreads();
        if (wid == 0) {
            int s = wsum[lane];
#pragma unroll
            for (int off = 1; off < 32; off <<= 1) {
                int y = __shfl_up_sync(0xffffffffu, s, off);
                if (lane >= off) s += y;
            }
            wsum[lane] = s;
        }
        __syncthreads();
        int excl = x - v + (wid > 0 ? wsum[wid - 1] : 0) + s_carry;
        int ctot = wsum[31];
        if (i < n) rptr[i] = excl;
        __syncthreads();
        if (tid == 0) s_carry += ctot;
        __syncthreads();
    }
    if (tid == 0) rptr[n] = s_carry;
}

// ---------------- CSR fill: G ----------------
__global__ void __launch_bounds__(256) k_fillG(const int* __restrict__ G,
                                               const float* __restrict__ gv) {
    unsigned e = blockIdx.x * 256u + threadIdx.x;
    if (e >= EG) return;
    int row = __ldg(G + e);
    int col = __ldg(G + EG + e);
    float v = __ldg(gv + e);
    int pos = g_rptrG[row] + atomicAdd(&g_curG[row], 1);
    g_epayG[pos] = make_float2(__int_as_float(col), v);
}

// ---------------- CSR fill: HAN ----------------
__global__ void __launch_bounds__(256) k_fillH(const int* __restrict__ edges, int E2,
                                               int n, int base, int rbase, int paybase) {
    unsigned t = blockIdx.x * 256u + threadIdx.x;
    if (t >= 2u * (unsigned)E2) return;
    int m = (t >= (unsigned)E2) ? 1 : 0;
    int e = (int)t - m * E2;
    int src = __ldg(edges + (size_t)m * 2 * E2 + e);
    int dst = __ldg(edges + (size_t)m * 2 * E2 + E2 + e);
    const int* rptr = g_rptrH + rbase + m * (n + 1);
    int pos = rptr[dst] + atomicAdd(&g_curH[base + m * n + dst], 1);
    g_hpay[paybase + m * E2 + pos] = src;
}

// ---------------- DCCF: CSR SpMM (gather, no atomics, writes gnn) ----------------
__global__ void __launch_bounds__(256) k_spmm_csr() {
    unsigned t = blockIdx.x * 256u + threadIdx.x;
    unsigned r = t >> 4;
    unsigned c = t & 15u;
    if (r >= NN) return;
    int s = g_rptrG[r], e = g_rptrG[r + 1];
    float4 acc = make_float4(0.f, 0.f, 0.f, 0.f);
    int i = s;
    for (; i + 2 <= e; i += 2) {
        float2 p0 = __ldg(&g_epayG[i]);
        float2 p1 = __ldg(&g_epayG[i + 1]);
        int c0 = __float_as_int(p0.x), c1 = __float_as_int(p1.x);
        float4 x0 = *(const float4*)(g_cur + (size_t)c0 * DD + c * 4);
        float4 x1 = *(const float4*)(g_cur + (size_t)c1 * DD + c * 4);
        acc.x += p0.y * x0.x + p1.y * x1.x;
        acc.y += p0.y * x0.y + p1.y * x1.y;
        acc.z += p0.y * x0.z + p1.y * x1.z;
        acc.w += p0.y * x0.w + p1.y * x1.w;
    }
    if (i < e) {
        float2 p0 = __ldg(&g_epayG[i]);
        int c0 = __float_as_int(p0.x);
        float4 x0 = *(const float4*)(g_cur + (size_t)c0 * DD + c * 4);
        acc.x += p0.y * x0.x; acc.y += p0.y * x0.y;
        acc.z += p0.y * x0.z; acc.w += p0.y * x0.w;
    }
    *(float4*)(g_gnn + (size_t)r * DD + c * 4) = acc;
}

// ---------------- DCCF: intent projection — row-pair f32x2 (unchanged from R4) ----------------
#define INTENT_SMEM 115712
#define IT_THREADS 256
#define IT_ROWS_PER_BLOCK 64

__global__ void __launch_bounds__(IT_THREADS) k_intent(const float* __restrict__ Wu,
                                                       const float* __restrict__ Wi) {
    extern __shared__ float sm[];
    const float4* Wp4 = (const float4*)sm;
    const float2* WTp = (const float2*)(sm + 8192);
    const int tid = threadIdx.x, w = tid >> 5, lane = tid & 31;

    ull* uT2 = (ull*)(sm + 16640) + w * 256;
    ull* pT2 = (ull*)(sm + 20736) + w * 512;

    const int UB = (NU + IT_ROWS_PER_BLOCK - 1) / IT_ROWS_PER_BLOCK;
    const bool isUser = (int)blockIdx.x < UB;
    const float* Wg = isUser ? Wu : Wi;
    const int rowbase = isUser ? (int)blockIdx.x * IT_ROWS_PER_BLOCK
                               : NU + ((int)blockIdx.x - UB) * IT_ROWS_PER_BLOCK;
    const int rowlim = isUser ? NU : NN;

    for (int t = tid; t < 2048; t += IT_THREADS) {
        ((float4*)sm)[t] = ((const float4*)Wg)[t];
    }
    __syncthreads();
    for (int t = tid; t < 4096; t += IT_THREADS) {
        int L = t >> 7, j = t & 127;
        ((float2*)(sm + 8192))[j * 33 + L] =
            make_float2(sm[(2 * L) * 128 + j], sm[(2 * L + 1) * 128 + j]);
    }
    __syncthreads();

    const int r0 = rowbase + w * 8;

    for (int t = lane; t < 256; t += 32) {
        int rho = t >> 6, k = t & 63;
        int ra = r0 + 2 * rho, rb = ra + 1;
        float xa = (ra < rowlim) ? g_cur[(size_t)ra * DD + k] : 0.f;
        float xb = (rb < rowlim) ? g_cur[(size_t)rb * DD + k] : 0.f;
        uT2[rho * 64 + k] = pack2(xa, xb);
    }
    __syncwarp();

    ull acc[4][4];
#pragma unroll
    for (int a = 0; a < 4; a++) { acc[a][0] = acc[a][1] = acc[a][2] = acc[a][3] = 0ull; }

    const ulonglong2* uT2v = (const ulonglong2*)uT2;
#pragma unroll 4
    for (int k2 = 0; k2 < 32; k2++) {
        float4 wa = Wp4[(2 * k2) * 32 + lane];
        float4 wb = Wp4[(2 * k2 + 1) * 32 + lane];
        ull sa0 = pk2(wa.x), sa1 = pk2(wa.y), sa2 = pk2(wa.z), sa3 = pk2(wa.w);
        ull sb0 = pk2(wb.x), sb1 = pk2(wb.y), sb2 = pk2(wb.z), sb3 = pk2(wb.w);
#pragma unroll
        for (int rho = 0; rho < 4; rho++) {
            ulonglong2 up = uT2v[rho * 32 + k2];
            fma2(acc[rho][0], sa0, up.x); fma2(acc[rho][1], sa1, up.x);
            fma2(acc[rho][2], sa2, up.x); fma2(acc[rho][3], sa3, up.x);
            fma2(acc[rho][0], sb0, up.y); fma2(acc[rho][1], sb1, up.y);
            fma2(acc[rho][2], sb2, up.y); fma2(acc[rho][3], sb3, up.y);
        }
    }

#pragma unroll
    for (int rho = 0; rho < 4; rho++) {
        float2 a0 = up2(acc[rho][0]), a1 = up2(acc[rho][1]);
        float2 a2 = up2(acc[rho][2]), a3 = up2(acc[rho][3]);
        float ml = fmaxf(fmaxf(a0.x, a1.x), fmaxf(a2.x, a3.x));
        float mh = fmaxf(fmaxf(a0.y, a1.y), fmaxf(a2.y, a3.y));
#pragma unroll
        for (int off = 16; off; off >>= 1) {
            ml = fmaxf(ml, __shfl_xor_sync(0xffffffffu, ml, off));
            mh = fmaxf(mh, __shfl_xor_sync(0xffffffffu, mh, off));
        }
        float el0 = __expf(a0.x - ml), el1 = __expf(a1.x - ml);
        float el2 = __expf(a2.x - ml), el3 = __expf(a3.x - ml);
        float eh0 = __expf(a0.y - mh), eh1 = __expf(a1.y - mh);
        float eh2 = __expf(a2.y - mh), eh3 = __expf(a3.y - mh);
        float sl = el0 + el1 + el2 + el3;
        float sh = eh0 + eh1 + eh2 + eh3;
#pragma unroll
        for (int off = 16; off; off >>= 1) {
            sl += __shfl_xor_sync(0xffffffffu, sl, off);
            sh += __shfl_xor_sync(0xffffffffu, sh, off);
        }
        float il = 1.f / sl, ih = 1.f / sh;
        ull q0 = pack2(el0 * il, eh0 * ih);
        ull q1 = pack2(el1 * il, eh1 * ih);
        ull q2 = pack2(el2 * il, eh2 * ih);
        ull q3 = pack2(el3 * il, eh3 * ih);
        ((ulonglong2*)pT2)[rho * 64 + 2 * lane] = make_ulonglong2(q0, q1);
        ((ulonglong2*)pT2)[rho * 64 + 2 * lane + 1] = make_ulonglong2(q2, q3);
    }
    __syncwarp();

    ull acc2[4][2];
#pragma unroll
    for (int a = 0; a < 4; a++) { acc2[a][0] = 0ull; acc2[a][1] = 0ull; }

    const ulonglong2* pT2v = (const ulonglong2*)pT2;
#pragma unroll 2
    for (int j4 = 0; j4 < 32; j4++) {
        ulonglong2 P0a = pT2v[0 * 64 + 2 * j4], P0b = pT2v[0 * 64 + 2 * j4 + 1];
        ulonglong2 P1a = pT2v[1 * 64 + 2 * j4], P1b = pT2v[1 * 64 + 2 * j4 + 1];
        ulonglong2 P2a = pT2v[2 * 64 + 2 * j4], P2b = pT2v[2 * 64 + 2 * j4 + 1];
        ulonglong2 P3a = pT2v[3 * 64 + 2 * j4], P3b = pT2v[3 * 64 + 2 * j4 + 1];
#define P2J(JJ, PW)                                             \
        {                                                       \
            float2 wt = WTp[(4 * j4 + JJ) * 33 + lane];         \
            ull s0 = pk2(wt.x), s1 = pk2(wt.y);                 \
            fma2(acc2[0][0], s0, P0##PW); fma2(acc2[0][1], s1, P0##PW); \
            fma2(acc2[1][0], s0, P1##PW); fma2(acc2[1][1], s1, P1##PW); \
            fma2(acc2[2][0], s0, P2##PW); fma2(acc2[2][1], s1, P2##PW); \
            fma2(acc2[3][0], s0, P3##PW); fma2(acc2[3][1], s1, P3##PW); \
        }
        P2J(0, a.x) P2J(1, a.y) P2J(2, b.x) P2J(3, b.y)
#undef P2J
    }

#pragma unroll
    for (int rho = 0; rho < 4; rho++) {
        float2 o0 = up2(acc2[rho][0]);
        float2 o1 = up2(acc2[rho][1]);
#pragma unroll
        for (int par = 0; par < 2; par++) {
            int r = r0 + 2 * rho + par;
            if (r >= rowlim) continue;
            float oa = par ? o0.y : o0.x;
            float ob = par ? o1.y : o1.x;
            size_t base = (size_t)r * DD + lane * 2;
            float2 cu = *(const float2*)(g_cur + base);
            float2 gn = *(const float2*)(g_gnn + base);
            float2 tt = *(const float2*)(g_total + base);
            float n0 = gn.x + oa + cu.x;
            float n1 = gn.y + ob + cu.y;
            *(float2*)(g_cur + base) = make_float2(n0, n1);
            *(float2*)(g_total + base) = make_float2(tt.x + n0, tt.y + n1);
        }
    }
}

// ---------------- HAN: CSR gather (both norm scalings fused, writes final z) ----------------
__global__ void __launch_bounds__(256) k_hgather(const float* __restrict__ feat, int E2,
                                                 int n, int base, int rbase, int paybase,
                                                 int zbase) {
    unsigned t = blockIdx.x * 256u + threadIdx.x;
    unsigned idx = t >> 4;
    unsigned c = t & 15u;
    if (idx >= 2u * (unsigned)n) return;
    int m = (idx >= (unsigned)n) ? 1 : 0;
    int node = (int)idx - m * n;
    const int* rptr = g_rptrH + rbase + m * (n + 1);
    int s = rptr[node], e = rptr[node + 1];
    const int* pay = g_hpay + paybase + m * E2;
    const int* dout = g_dout + base + m * n;
    float4 acc = make_float4(0.f, 0.f, 0.f, 0.f);
    int i = s;
    for (; i + 2 <= e; i += 2) {
        int s0 = __ldg(pay + i), s1 = __ldg(pay + i + 1);
        float w0 = rsqrtf((float)__ldg(dout + s0));
        float w1 = rsqrtf((float)__ldg(dout + s1));
        float4 x0 = *(const float4*)(feat + (size_t)s0 * DD + c * 4);
        float4 x1 = *(const float4*)(feat + (size_t)s1 * DD + c * 4);
        acc.x += w0 * x0.x + w1 * x1.x;
        acc.y += w0 * x0.y + w1 * x1.y;
        acc.z += w0 * x0.z + w1 * x1.z;
        acc.w += w0 * x0.w + w1 * x1.w;
    }
    if (i < e) {
        int s0 = __ldg(pay + i);
        float w0 = rsqrtf((float)__ldg(dout + s0));
        float4 x0 = *(const float4*)(feat + (size_t)s0 * DD + c * 4);
        acc.x += w0 * x0.x; acc.y += w0 * x0.y;
        acc.z += w0 * x0.z; acc.w += w0 * x0.w;
    }
    float din = (float)(e - s);
    float sc = (din > 0.f) ? rsqrtf(din) : 0.f;
    *(float4*)(g_z + (size_t)zbase + ((size_t)node * 2 + m) * DD + c * 4) =
        make_float4(acc.x * sc, acc.y * sc, acc.z * sc, acc.w * sc);
}

// ---------------- HAN: semantic attention logits (z already final) ----------------
__global__ void __launch_bounds__(256) k_han_node(const float* __restrict__ W1g,
                                                  const float* __restrict__ b1g,
                                                  const float* __restrict__ w2g,
                                                  int n, int zbase, int wbase) {
    __shared__ float Wsm[8192];
    __shared__ float ush[4096];
    __shared__ float bsh[128];
    __shared__ float w2sh[128];
    __shared__ float wacc[2];

    const int tid = threadIdx.x, w = tid >> 5, lane = tid & 31;
    for (int t = tid; t < 2048; t += 256) {
        int k = t >> 5, L = t & 31;
        ((float4*)Wsm)[t] = *(const float4*)(W1g + k * 128 + L * 4);
    }
    if (tid < 128) { bsh[tid] = b1g[tid]; w2sh[tid] = w2g[tid]; }
    if (tid < 2) wacc[tid] = 0.f;
    __syncthreads();

    const int rows = 2 * n;
    const int r0 = (int)blockIdx.x * 64 + w * 8;
    float* u = ush + w * 512;

    for (int t = lane; t < 512; t += 32) {
        int rr = t >> 6, d = t & 63;
        int row = r0 + rr;
        u[t] = (row < rows) ? g_z[(size_t)zbase + (size_t)row * DD + d] : 0.f;
    }
    __syncwarp();

    float acc[8][4];
#pragma unroll
    for (int a = 0; a < 8; a++) { acc[a][0] = acc[a][1] = acc[a][2] = acc[a][3] = 0.f; }

#pragma unroll 2
    for (int kk = 0; kk < 16; kk++) {
        float4 w0 = ((const float4*)Wsm)[(4 * kk + 0) * 32 + lane];
        float4 w1 = ((const float4*)Wsm)[(4 * kk + 1) * 32 + lane];
        float4 w2 = ((const float4*)Wsm)[(4 * kk + 2) * 32 + lane];
        float4 w3 = ((const float4*)Wsm)[(4 * kk + 3) * 32 + lane];
#pragma unroll
        for (int rr = 0; rr < 8; rr++) {
            float4 uv = *(const float4*)(u + rr * 64 + kk * 4);
            acc[rr][0] += uv.x * w0.x + uv.y * w1.x + uv.z * w2.x + uv.w * w3.x;
            acc[rr][1] += uv.x * w0.y + uv.y * w1.y + uv.z * w2.y + uv.w * w3.y;
            acc[rr][2] += uv.x * w0.z + uv.y * w1.z + uv.z * w2.z + uv.w * w3.z;
            acc[rr][3] += uv.x * w0.w + uv.y * w1.w + uv.z * w2.w + uv.w * w3.w;
        }
    }

    float wl01[2] = {0.f, 0.f};
#pragma unroll
    for (int rr = 0; rr < 8; rr++) {
        int row = r0 + rr;
        float wl = 0.f;
#pragma unroll
        for (int c = 0; c < 4; c++) {
            int j = lane * 4 + c;
            wl += tanhf(acc[rr][c] + bsh[j]) * w2sh[j];
        }
        if (row < rows) wl01[row & 1] += wl;
    }
#pragma unroll
    for (int off = 16; off; off >>= 1) {
        wl01[0] += __shfl_xor_sync(0xffffffffu, wl01[0], off);
        wl01[1] += __shfl_xor_sync(0xffffffffu, wl01[1], off);
    }
    if (lane == 0) {
        atomicAdd(&wacc[0], wl01[0]);
        atomicAdd(&wacc[1], wl01[1]);
    }
    __syncthreads();
    if (tid < 2) atomicAdd(&g_wsum[wbase + tid], wacc[tid]);
}

// ---------------- final combine: 0.5*dccf + 0.5*han ----------------
__global__ void __launch_bounds__(256) k_combine(float* __restrict__ out) {
    unsigned i = blockIdx.x * 256u + threadIdx.x;
    if (i >= (unsigned)(NN * DD)) return;
    unsigned node = i >> 6, d = i & 63u;
    float w0, w1;
    size_t zr;
    if (node < NU) {
        w0 = g_wsum[0] * (1.f / NU);
        w1 = g_wsum[1] * (1.f / NU);
        zr = (size_t)node * 128;
    } else {
        w0 = g_wsum[2] * (1.f / NI);
        w1 = g_wsum[3] * (1.f / NI);
        zr = (size_t)NU * 128 + (size_t)(node - NU) * 128;
    }
    float mx = fmaxf(w0, w1);
    float e0 = __expf(w0 - mx), e1 = __expf(w1 - mx);
    float inv = 1.f / (e0 + e1);
    float han = (e0 * inv) * g_z[zr + d] + (e1 * inv) * g_z[zr + 64 + d];
    out[i] = 0.5f * g_total[i] + 0.5f * han;
}

// ---------------- launcher ----------------
extern "C" void kernel_launch(void* const* d_in, const int* in_sizes, int n_in,
                              void* d_out, int out_size) {
    const int*   G    = (const int*)d_in[0];
    const float* Gv   = (const float*)d_in[1];
    const float* fu   = (const float*)d_in[2];
    const float* fi   = (const float*)d_in[3];
    const float* Wu   = (const float*)d_in[4];
    const float* Wi   = (const float*)d_in[5];
    const int*   eu   = (const int*)d_in[6];
    const int*   ei   = (const int*)d_in[7];
    const float* suW1 = (const float*)d_in[8];
    const float* sub1 = (const float*)d_in[9];
    const float* suw2 = (const float*)d_in[10];
    const float* siW1 = (const float*)d_in[11];
    const float* sib1 = (const float*)d_in[12];
    const float* siw2 = (const float*)d_in[13];
    float* out = (float*)d_out;

    cudaFuncSetAttribute(k_intent, cudaFuncAttributeMaxDynamicSharedMemorySize, INTENT_SMEM);

    const int UB = (NU + IT_ROWS_PER_BLOCK - 1) / IT_ROWS_PER_BLOCK;
    const int IB = (NI + IT_ROWS_PER_BLOCK - 1) / IT_ROWS_PER_BLOCK;

    // init + CSR build
    k_zero_cnt<<<1172, 256>>>();
    k_init<<<37500, 256>>>(fu, fi);
    k_histG<<<12500, 256>>>(G);
    k_histH<<<12500, 256>>>(eu, EU_, NU, 0);
    k_histH<<<6250, 256>>>(ei, EI_, NI, 2 * NU);
    k_scan<<<5, 1024>>>();
    k_fillG<<<12500, 256>>>(G, Gv);
    k_fillH<<<12500, 256>>>(eu, EU_, NU, 0, 0, 0);
    k_fillH<<<6250, 256>>>(ei, EI_, NI, 2 * NU, 2 * (NU + 1), 2 * EU_);

    // DCCF layers
    for (int layer = 0; layer < 2; layer++) {
        k_spmm_csr<<<9375, 256>>>();
        k_intent<<<UB + IB, IT_THREADS, INTENT_SMEM>>>(Wu, Wi);
    }

    // HAN
    k_hgather<<<12500, 256>>>(fu, EU_, NU, 0, 0, 0, 0);
    k_hgather<<<6250, 256>>>(fi, EI_, NI, 2 * NU, 2 * (NU + 1), 2 * EU_, NU * 128);
    k_han_node<<<3125, 256>>>(suW1, sub1, suw2, NU, 0, 0);
    k_han_node<<<1563, 256>>>(siW1, sib1, siw2, NI, NU * 128, 2);
    k_combine<<<37500, 256>>>(out);
}